// round 10
// baseline (speedup 1.0000x reference)
#include <cuda_runtime.h>
#include <cstdint>

// Q = L @ L^T, L lower-triangular 3x3 from packed [a,b,c,d,e,f]:
//   Q00=a*a  Q01=a*b      Q02=a*d
//   Q10=a*b  Q11=b*b+c*c  Q12=b*d+c*e
//   Q20=a*d  Q21=b*d+c*e  Q22=d*d+e*e+f*f
//
// 3-tile pipeline with ONE BLOCK-WIDE 27KB ASYNC BULK STORE.
// Loads: front-batched cp.async.cg (9 x 16B per lane, 3 commit groups),
// warp-autonomous compute (each warp's 64-row slice is self-contained) into
// one contiguous 27KB smem output region. A single cp.async.bulk per block
// then presents DRAM with large strictly-sequential write bursts (fewer
// R/W turnarounds) — the lever that produced the R9 win, scaled 1.5x.

#define TPB 128
#define ROWS_PB 256
#define TILES_PB 3
#define IN_F4 (ROWS_PB * 6 / 4)        // 384 f4/tile ; per warp: 96 (3/lane)
#define TILE_OUT_FLOATS (ROWS_PB * 9)  // 2304 floats = 9216 B per tile
#define W_IN 96
#define W_ROWS 64
#define W_OUT_FLOATS (W_ROWS * 9)      // 576 floats

__device__ __forceinline__ void cp_async16(uint32_t saddr, const void* gaddr) {
    asm volatile("cp.async.cg.shared.global [%0], [%1], 16;\n" :: "r"(saddr), "l"(gaddr));
}
__device__ __forceinline__ void cp_commit() {
    asm volatile("cp.async.commit_group;\n" ::: "memory");
}
template <int N>
__device__ __forceinline__ void cp_wait() {
    asm volatile("cp.async.wait_group %0;\n" :: "n"(N) : "memory");
}

// Async bulk store: smem (shared::cta) -> gmem, tracked by bulk groups.
__device__ __forceinline__ void bulk_store(void* gaddr, uint32_t saddr, uint32_t bytes) {
    asm volatile("cp.async.bulk.global.shared::cta.bulk_group [%0], [%1], %2;\n"
                 :: "l"(gaddr), "r"(saddr), "r"(bytes) : "memory");
}
__device__ __forceinline__ void bulk_commit() {
    asm volatile("cp.async.bulk.commit_group;\n" ::: "memory");
}
template <int N>
__device__ __forceinline__ void bulk_wait() {
    asm volatile("cp.async.bulk.wait_group %0;\n" :: "n"(N) : "memory");
}
__device__ __forceinline__ void fence_async_shared() {
    asm volatile("fence.proxy.async.shared::cta;\n" ::: "memory");
}

__device__ __forceinline__ void row_to_q(const float* __restrict__ v, float* __restrict__ o) {
    const float a = v[0], b = v[1], c = v[2], d = v[3], e = v[4], f = v[5];
    const float ab = a * b;
    const float ad = a * d;
    const float bdce = fmaf(b, d, c * e);
    o[0] = a * a;
    o[1] = ab;
    o[2] = ad;
    o[3] = ab;
    o[4] = fmaf(b, b, c * c);
    o[5] = bdce;
    o[6] = ad;
    o[7] = bdce;
    o[8] = fmaf(d, d, fmaf(e, e, f * f));
}

// Compute this warp's 64 rows of one tile: smem input slice -> smem output slice.
__device__ __forceinline__ void warp_compute(const float* __restrict__ sin_w,
                                             float* __restrict__ sout_w, int l)
{
#pragma unroll
    for (int j = 0; j < 2; j++) {
        const int r = l + 32 * j;
        float v[6], o[9];
#pragma unroll
        for (int k = 0; k < 6; k++) v[k] = sin_w[r * 6 + k];
        row_to_q(v, o);
#pragma unroll
        for (int k = 0; k < 9; k++) sout_w[r * 9 + k] = o[k];
    }
}

__global__ __launch_bounds__(TPB) void chol_to_cov_bulk3(const float4* __restrict__ in4,
                                                         float* __restrict__ out,
                                                         int num_tiles)
{
    __shared__ float4 s_in[TILES_PB][IN_F4];              // 18 KB
    __shared__ float  s_out[TILES_PB * TILE_OUT_FLOATS];  // 27 KB, contiguous

    const int t = threadIdx.x;
    const int w = t >> 5;
    const int l = t & 31;

    const int tile0 = blockIdx.x * TILES_PB;
    const int nt = (num_tiles - tile0 < TILES_PB) ? (num_tiles - tile0) : TILES_PB;

    // Issue this warp's input slices; one commit group per tile slot
    // (empty groups for missing tiles complete immediately).
#pragma unroll
    for (int i = 0; i < TILES_PB; i++) {
        if (i < nt) {
            const float4* ip = in4 + (size_t)(tile0 + i) * IN_F4 + w * W_IN;
            uint32_t sb = (uint32_t)__cvta_generic_to_shared(&s_in[i][w * W_IN]);
#pragma unroll
            for (int k = 0; k < 3; k++)
                cp_async16(sb + (l + 32 * k) * 16u, ip + l + 32 * k);
        }
        cp_commit();
    }

    // ---- Tile 0 ----
    cp_wait<2>();
    __syncwarp();
    warp_compute(reinterpret_cast<const float*>(&s_in[0][w * W_IN]),
                 &s_out[w * W_OUT_FLOATS], l);

    // ---- Tile 1 ----
    if (nt > 1) {
        cp_wait<1>();
        __syncwarp();
        warp_compute(reinterpret_cast<const float*>(&s_in[1][w * W_IN]),
                     &s_out[TILE_OUT_FLOATS + w * W_OUT_FLOATS], l);
    }

    // ---- Tile 2 ----
    if (nt > 2) {
        cp_wait<0>();
        __syncwarp();
        warp_compute(reinterpret_cast<const float*>(&s_in[2][w * W_IN]),
                     &s_out[2 * TILE_OUT_FLOATS + w * W_OUT_FLOATS], l);
    }

    // One large sequential bulk store for the whole block output.
    fence_async_shared();
    __syncthreads();
    if (t == 0) {
        bulk_store(out + (size_t)tile0 * TILE_OUT_FLOATS,
                   (uint32_t)__cvta_generic_to_shared(&s_out[0]),
                   (uint32_t)nt * TILE_OUT_FLOATS * 4u);
        bulk_commit();
        bulk_wait<0>();  // keep smem alive until the bulk engine has read it
    }
}

// Scalar tail for the (< ROWS_PB) remainder rows.
__global__ void chol_to_cov_tail(const float* __restrict__ in,
                                 float* __restrict__ out,
                                 int start_row, int n_rows)
{
    const int r = start_row + blockIdx.x * blockDim.x + threadIdx.x;
    if (r >= n_rows) return;
    float v[6], o[9];
#pragma unroll
    for (int k = 0; k < 6; k++) v[k] = in[(size_t)r * 6 + k];
    row_to_q(v, o);
#pragma unroll
    for (int k = 0; k < 9; k++) out[(size_t)r * 9 + k] = o[k];
}

extern "C" void kernel_launch(void* const* d_in, const int* in_sizes, int n_in,
                              void* d_out, int out_size)
{
    const float* in = (const float*)d_in[0];
    float* out = (float*)d_out;
    const int n_rows = in_sizes[0] / 6;

    const int num_tiles = n_rows / ROWS_PB;
    if (num_tiles > 0) {
        const int blocks = (num_tiles + TILES_PB - 1) / TILES_PB;
        chol_to_cov_bulk3<<<blocks, TPB>>>((const float4*)in, out, num_tiles);
    }
    const int done = num_tiles * ROWS_PB;
    if (done < n_rows) {
        const int rem = n_rows - done;
        chol_to_cov_tail<<<(rem + 127) / 128, 128>>>(in, out, done, n_rows);
    }
}